// round 2
// baseline (speedup 1.0000x reference)
#include <cuda_runtime.h>
#include <math.h>
#include <stdint.h>

#define Nq 8192
#define Kc 8192
#define Dd 512
#define Mq (2*Nq)

// ---------------- device scratch (static; no allocations) ----------------
__device__ float g_codebook[Kc*Dd];   // [K,D] projected codebook
__device__ float g_cbsq[Kc];          // ||c_k||^2
__device__ float g_bd[2*Mq];          // best dist per (ksplit,row)
__device__ int   g_bi[2*Mq];          // best idx  per (ksplit,row)
__device__ int   g_counts[2*Kc];      // histogram per source
__device__ float g_rowsums[Mq*2];     // per-row (mse_self, mse_cross) partial sums

// ---------------- reset (device globals persist across graph replays) ----
__global__ void reset_kernel() {
    int i = blockIdx.x * 256 + threadIdx.x;
    if (i < 2*Kc) g_counts[i] = 0;
}

// ---------------- codebook GEMM: C[k][d] = emb[k,:]·pw[d,:] + b[d] -------
__global__ __launch_bounds__(256) void codebook_gemm(
    const float* __restrict__ emb, const float* __restrict__ pw,
    const float* __restrict__ pb)
{
    __shared__ float Es[16][64];
    __shared__ float Ps[16][64];
    const int tid = threadIdx.x;
    const int tx = tid & 15, ty = tid >> 4;
    const int kb = blockIdx.x * 64, db = blockIdx.y * 64;
    const int lr = tid & 63, jq = tid >> 6;   // loader: row-in-tile, quad-of-16

    float acc[4][4];
    #pragma unroll
    for (int i = 0; i < 4; i++)
        #pragma unroll
        for (int j = 0; j < 4; j++) acc[i][j] = 0.f;

    for (int j0 = 0; j0 < Dd; j0 += 16) {
        float4 ve = *(const float4*)(emb + (size_t)(kb+lr)*Dd + j0 + jq*4);
        Es[jq*4+0][lr]=ve.x; Es[jq*4+1][lr]=ve.y; Es[jq*4+2][lr]=ve.z; Es[jq*4+3][lr]=ve.w;
        float4 vp = *(const float4*)(pw  + (size_t)(db+lr)*Dd + j0 + jq*4);
        Ps[jq*4+0][lr]=vp.x; Ps[jq*4+1][lr]=vp.y; Ps[jq*4+2][lr]=vp.z; Ps[jq*4+3][lr]=vp.w;
        __syncthreads();
        #pragma unroll
        for (int jj = 0; jj < 16; jj++) {
            float4 a = *(const float4*)&Es[jj][ty*4];
            float4 b = *(const float4*)&Ps[jj][tx*4];
            float ar[4] = {a.x,a.y,a.z,a.w};
            float br[4] = {b.x,b.y,b.z,b.w};
            #pragma unroll
            for (int i = 0; i < 4; i++)
                #pragma unroll
                for (int j = 0; j < 4; j++)
                    acc[i][j] = fmaf(ar[i], br[j], acc[i][j]);
        }
        __syncthreads();
    }
    #pragma unroll
    for (int j = 0; j < 4; j++) {
        float bias = pb[db + tx*4 + j];
        #pragma unroll
        for (int i = 0; i < 4; i++)
            g_codebook[(size_t)(kb + ty*4 + i)*Dd + db + tx*4 + j] = acc[i][j] + bias;
    }
}

// ---------------- cb_sq: one warp per codebook row ------------------------
__global__ void cbsq_kernel() {
    int row  = blockIdx.x * 8 + (threadIdx.x >> 5);
    int lane = threadIdx.x & 31;
    const float* c = g_codebook + (size_t)row * Dd;
    float s = 0.f;
    for (int d = lane*4; d < Dd; d += 128) {
        float4 v = *(const float4*)(c + d);
        s += v.x*v.x + v.y*v.y + v.z*v.z + v.w*v.w;
    }
    #pragma unroll
    for (int off = 16; off; off >>= 1) s += __shfl_down_sync(0xffffffffu, s, off);
    if (lane == 0) g_cbsq[row] = s;
}

// ---------------- argmin: 128x128 tile, 8x8/thread via FFMA2 --------------
// Accumulators packed as f32x2 along the codebook (j) axis; the Cs tile's
// column pairs are contiguous so a 16B shared load yields packed operands
// for free. X values are broadcast-packed once per (dd,i) on the ALU pipe.
#define BM 128
#define BN 128
#define BD 8
__global__ __launch_bounds__(256, 2) void argmin_kernel(
    const float* __restrict__ X0, const float* __restrict__ X1)
{
    __shared__ float Xs[BD][BM];
    __shared__ float Cs[BD][BN];
    __shared__ float sD[BM][16];
    __shared__ int   sI[BM][16];

    const int tid = threadIdx.x;
    const int tx = tid & 15, ty = tid >> 4;
    const int m0 = blockIdx.x * BM;
    const float* X = (m0 < Nq) ? (X0 + (size_t)m0*Dd) : (X1 + (size_t)(m0-Nq)*Dd);
    const int k0 = blockIdx.y * (Kc/2);
    const int ml = tid & 127, dq = tid >> 7;

    float bd[8]; int bi[8];
    #pragma unroll
    for (int i = 0; i < 8; i++) { bd[i] = INFINITY; bi[i] = 0; }

    for (int kc = 0; kc < Kc/2; kc += BN) {
        unsigned long long acc2[8][4];   // [x-row][j-pair], each = packed f32x2
        #pragma unroll
        for (int i = 0; i < 8; i++)
            #pragma unroll
            for (int j = 0; j < 4; j++) acc2[i][j] = 0ull;

        for (int d0 = 0; d0 < Dd; d0 += BD) {
            float4 vx = *(const float4*)(X + (size_t)ml*Dd + d0 + dq*4);
            Xs[dq*4+0][ml]=vx.x; Xs[dq*4+1][ml]=vx.y; Xs[dq*4+2][ml]=vx.z; Xs[dq*4+3][ml]=vx.w;
            float4 vc = *(const float4*)(g_codebook + (size_t)(k0+kc+ml)*Dd + d0 + dq*4);
            Cs[dq*4+0][ml]=vc.x; Cs[dq*4+1][ml]=vc.y; Cs[dq*4+2][ml]=vc.z; Cs[dq*4+3][ml]=vc.w;
            __syncthreads();
            #pragma unroll
            for (int dd = 0; dd < BD; dd++) {
                ulonglong2 ca = *(const ulonglong2*)&Cs[dd][tx*4];      // pairs (tx*4,+1),(+2,+3)
                ulonglong2 cb = *(const ulonglong2*)&Cs[dd][64 + tx*4]; // pairs (64+tx*4,+1),(+2,+3)
                unsigned long long cp[4] = {ca.x, ca.y, cb.x, cb.y};
                float4 xa = *(const float4*)&Xs[dd][ty*4];
                float4 xb = *(const float4*)&Xs[dd][64 + ty*4];
                float xr[8] = {xa.x,xa.y,xa.z,xa.w, xb.x,xb.y,xb.z,xb.w};
                #pragma unroll
                for (int i = 0; i < 8; i++) {
                    unsigned long long xp;
                    asm("mov.b64 %0, {%1, %1};" : "=l"(xp) : "f"(xr[i]));
                    #pragma unroll
                    for (int j = 0; j < 4; j++)
                        asm("fma.rn.f32x2 %0, %1, %2, %0;"
                            : "+l"(acc2[i][j]) : "l"(xp), "l"(cp[j]));
                }
            }
            __syncthreads();
        }
        // epilogue: dist = cbsq - 2*dot ; running lexicographic min per row
        #pragma unroll
        for (int jp = 0; jp < 4; jp++) {
            int base = (jp < 2) ? (tx*4 + jp*2) : (64 + tx*4 + (jp-2)*2);
            int kk0 = k0 + kc + base;
            float cq0 = g_cbsq[kk0];
            float cq1 = g_cbsq[kk0 + 1];
            #pragma unroll
            for (int i = 0; i < 8; i++) {
                float lo, hi;
                asm("mov.b64 {%0, %1}, %2;" : "=f"(lo), "=f"(hi) : "l"(acc2[i][jp]));
                float dist0 = fmaf(-2.f, lo, cq0);
                float dist1 = fmaf(-2.f, hi, cq1);
                if (dist0 < bd[i]) { bd[i] = dist0; bi[i] = kk0; }
                if (dist1 < bd[i]) { bd[i] = dist1; bi[i] = kk0 + 1; }
            }
        }
    }

    // single cross-thread reduction at the end
    #pragma unroll
    for (int i = 0; i < 8; i++) {
        int ri = (i < 4) ? (ty*4 + i) : (64 + ty*4 + (i-4));
        sD[ri][tx] = bd[i]; sI[ri][tx] = bi[i];
    }
    __syncthreads();
    if (tid < BM) {
        float best = sD[tid][0]; int bidx = sI[tid][0];
        #pragma unroll
        for (int t = 1; t < 16; t++) {
            float dv = sD[tid][t]; int iv = sI[tid][t];
            if (dv < best || (dv == best && iv < bidx)) { best = dv; bidx = iv; }
        }
        g_bd[blockIdx.y*Mq + m0 + tid] = best;
        g_bi[blockIdx.y*Mq + m0 + tid] = bidx;
    }
}

// ---------------- finalize idx, gather row, per-row MSE partials ----------
__global__ void gather_kernel(const float* __restrict__ X0,
                              const float* __restrict__ X1,
                              float* __restrict__ out)
{
    const int m = blockIdx.x;
    const int tid = threadIdx.x;        // 128 threads, 4 floats each
    __shared__ int s_idx;
    __shared__ float wsum[4][2];

    if (tid == 0) {
        float d0 = g_bd[m], d1 = g_bd[Mq + m];
        int   i0 = g_bi[m], i1 = g_bi[Mq + m];
        int idx = (d1 < d0) ? i1 : i0;   // split0 always has the lower indices
        s_idx = idx;
        int src = (m < Nq) ? 0 : 1;
        atomicAdd(&g_counts[src*Kc + idx], 1);
    }
    __syncthreads();
    const int idx = s_idx;
    const float* q = g_codebook + (size_t)idx * Dd;
    const float *x, *o; float* op;
    if (m < Nq) { x = X0 + (size_t)m*Dd;      o = X1 + (size_t)m*Dd;      op = out + (size_t)m*Dd; }
    else { int mr = m - Nq;
           x = X1 + (size_t)mr*Dd;            o = X0 + (size_t)mr*Dd;     op = out + (size_t)(Nq+mr)*Dd; }

    float4 qv = *(const float4*)(q + tid*4);
    float4 xv = *(const float4*)(x + tid*4);
    float4 ov = *(const float4*)(o + tid*4);
    // straight-through forward value: x + (q - x), matching reference fp order
    float dx0 = qv.x - xv.x, dx1 = qv.y - xv.y, dx2 = qv.z - xv.z, dx3 = qv.w - xv.w;
    float4 w = {xv.x + dx0, xv.y + dx1, xv.z + dx2, xv.w + dx3};
    *(float4*)(op + tid*4) = w;

    float sA = dx0*dx0 + dx1*dx1 + dx2*dx2 + dx3*dx3;          // (q - x)^2
    float e0 = qv.x - ov.x, e1 = qv.y - ov.y, e2 = qv.z - ov.z, e3 = qv.w - ov.w;
    float sB = e0*e0 + e1*e1 + e2*e2 + e3*e3;                   // (q - other)^2
    #pragma unroll
    for (int off = 16; off; off >>= 1) {
        sA += __shfl_down_sync(0xffffffffu, sA, off);
        sB += __shfl_down_sync(0xffffffffu, sB, off);
    }
    int warp = tid >> 5, lane = tid & 31;
    if (lane == 0) { wsum[warp][0] = sA; wsum[warp][1] = sB; }
    __syncthreads();
    if (tid == 0) {
        g_rowsums[2*m]   = wsum[0][0] + wsum[1][0] + wsum[2][0] + wsum[3][0];
        g_rowsums[2*m+1] = wsum[0][1] + wsum[1][1] + wsum[2][1] + wsum[3][1];
    }
}

// ---------------- scalar losses (deterministic fixed-order reduce) --------
__global__ void loss_kernel(float* __restrict__ out) {
    const int t = threadIdx.x;   // 256
    __shared__ double red[4][256];
    double es = 0, csr = 0, er = 0, crs = 0;
    for (int m = t; m < Nq; m += 256)      { es  += (double)g_rowsums[2*m]; csr += (double)g_rowsums[2*m+1]; }
    for (int m = Nq + t; m < Mq; m += 256) { er  += (double)g_rowsums[2*m]; crs += (double)g_rowsums[2*m+1]; }
    red[0][t]=es; red[1][t]=csr; red[2][t]=er; red[3][t]=crs;
    __syncthreads();
    for (int off = 128; off; off >>= 1) {
        if (t < off) {
            red[0][t]+=red[0][t+off]; red[1][t]+=red[1][t+off];
            red[2][t]+=red[2][t+off]; red[3][t]+=red[3][t+off];
        }
        __syncthreads();
    }
    if (t == 0) {
        const double nd = (double)Nq * (double)Dd;
        double Es = red[0][0]/nd, Csr = red[1][0]/nd, Er = red[2][0]/nd, Crs = red[3][0]/nd;
        out[(size_t)2*Nq*Dd + 0] = (float)(0.5 * Es);                       // scRNA_loss
        double fwd = Er + Es + 0.5*Crs + 0.5*Csr;
        out[(size_t)2*Nq*Dd + 1] = (float)(0.5*Er + 0.25*fwd);              // ribo_loss
    }
}

// ---------------- perplexity per source -----------------------------------
__global__ void perp_kernel(float* __restrict__ out) {
    const int src = blockIdx.x;
    const int t = threadIdx.x;   // 256
    __shared__ float red[256];
    float h = 0.f;
    for (int k = t; k < Kc; k += 256) {
        float p = (float)g_counts[src*Kc + k] * (1.0f/(float)Nq);
        h += p * logf(p + 1e-10f);
    }
    red[t] = h;
    __syncthreads();
    for (int off = 128; off; off >>= 1) {
        if (t < off) red[t] += red[t+off];
        __syncthreads();
    }
    if (t == 0) out[(size_t)2*Nq*Dd + 2 + src] = expf(-red[0]);
}

// ---------------- launcher -------------------------------------------------
extern "C" void kernel_launch(void* const* d_in, const int* in_sizes, int n_in,
                              void* d_out, int out_size)
{
    const float* scRNA = (const float*)d_in[0];   // [N,D]
    const float* ribo  = (const float*)d_in[1];   // [N,D]
    const float* emb   = (const float*)d_in[2];   // [K,D]
    const float* pw    = (const float*)d_in[3];   // [D,D]
    const float* pb    = (const float*)d_in[4];   // [D]
    float* out = (float*)d_out;

    reset_kernel<<<(2*Kc + 255)/256, 256>>>();
    codebook_gemm<<<dim3(Kc/64, Dd/64), 256>>>(emb, pw, pb);
    cbsq_kernel<<<Kc/8, 256>>>();
    argmin_kernel<<<dim3(Mq/BM, 2), 256>>>(scRNA, ribo);
    gather_kernel<<<Mq, 128>>>(scRNA, ribo, out);
    loss_kernel<<<1, 256>>>(out);
    perp_kernel<<<2, 256>>>(out);
}

// round 5
// speedup vs baseline: 2.8011x; 2.8011x over previous
#include <cuda_runtime.h>
#include <cuda_fp16.h>
#include <math.h>
#include <stdint.h>

#define Nq 8192
#define Kc 8192
#define Dd 512
#define Mq (2*Nq)

// ---- mma-argmin tiling ----
#define MT 128                 // queries per CTA
#define NTB 128                // codes per N-chunk
#define NCB (Kc/NTB)           // 64
#define KCH 64                 // halfs per K chunk (128B rows)
#define KIT (Dd/KCH)           // 8
#define NCHUNKS (NCB*KIT)      // 512 pipeline steps
#define STAGE_BYTES 65536
#define T_XH 0
#define T_XL 16384
#define T_CH 32768
#define T_CL 49152
#define DSM_BYTES (2*STAGE_BYTES + 1024)

// ---------------- device scratch ----------------
__device__ float  g_codebook[Kc*Dd];
__device__ __half g_chi[Kc*Dd];
__device__ __half g_clo[Kc*Dd];
__device__ __half g_xhi[(size_t)Mq*Dd];
__device__ __half g_xlo[(size_t)Mq*Dd];
__device__ float  g_cbsq[Kc];
__device__ int    g_bi[Mq];
__device__ int    g_counts[2*Kc];
__device__ float  g_rowsums[Mq*2];

// ---------------- helpers ----------------
__device__ __forceinline__ uint32_t smem_u32(const void* p) {
    uint32_t a;
    asm("{ .reg .u64 t; cvta.to.shared.u64 t, %1; cvt.u32.u64 %0, t; }" : "=r"(a) : "l"(p));
    return a;
}
#define SWZ(o) ((o) ^ (((o) >> 3) & 0x70))
#define CP_ASYNC16(dst, src) \
    asm volatile("cp.async.cg.shared.global [%0], [%1], 16;" :: "r"(dst), "l"(src) : "memory")
#define CP_COMMIT() asm volatile("cp.async.commit_group;" ::: "memory")
#define CP_WAIT0()  asm volatile("cp.async.wait_group 0;" ::: "memory")
#define LDSM_X4(r0,r1,r2,r3,a) \
    asm volatile("ldmatrix.sync.aligned.m8n8.x4.shared.b16 {%0,%1,%2,%3}, [%4];" \
        : "=r"(r0),"=r"(r1),"=r"(r2),"=r"(r3) : "r"(a))
#define MMA16816(d,a,b) \
    asm volatile("mma.sync.aligned.m16n8k16.row.col.f32.f16.f16.f32 " \
        "{%0,%1,%2,%3}, {%4,%5,%6,%7}, {%8,%9}, {%0,%1,%2,%3};" \
        : "+f"((d)[0]),"+f"((d)[1]),"+f"((d)[2]),"+f"((d)[3]) \
        : "r"((a)[0]),"r"((a)[1]),"r"((a)[2]),"r"((a)[3]), "r"((b)[0]),"r"((b)[1]))

// ---------------- reset ----------------
__global__ void reset_kernel() {
    int i = blockIdx.x * 256 + threadIdx.x;
    if (i < 2*Kc) g_counts[i] = 0;
}

// ---------------- codebook GEMM (scalar, small) ----------------
__global__ __launch_bounds__(256) void codebook_gemm(
    const float* __restrict__ emb, const float* __restrict__ pw,
    const float* __restrict__ pb)
{
    __shared__ float Es[16][64];
    __shared__ float Ps[16][64];
    const int tid = threadIdx.x;
    const int tx = tid & 15, ty = tid >> 4;
    const int kb = blockIdx.x * 64, db = blockIdx.y * 64;
    const int lr = tid & 63, jq = tid >> 6;
    float acc[4][4];
    #pragma unroll
    for (int i = 0; i < 4; i++)
        #pragma unroll
        for (int j = 0; j < 4; j++) acc[i][j] = 0.f;
    for (int j0 = 0; j0 < Dd; j0 += 16) {
        float4 ve = *(const float4*)(emb + (size_t)(kb+lr)*Dd + j0 + jq*4);
        Es[jq*4+0][lr]=ve.x; Es[jq*4+1][lr]=ve.y; Es[jq*4+2][lr]=ve.z; Es[jq*4+3][lr]=ve.w;
        float4 vp = *(const float4*)(pw  + (size_t)(db+lr)*Dd + j0 + jq*4);
        Ps[jq*4+0][lr]=vp.x; Ps[jq*4+1][lr]=vp.y; Ps[jq*4+2][lr]=vp.z; Ps[jq*4+3][lr]=vp.w;
        __syncthreads();
        #pragma unroll
        for (int jj = 0; jj < 16; jj++) {
            float4 a = *(const float4*)&Es[jj][ty*4];
            float4 b = *(const float4*)&Ps[jj][tx*4];
            float ar[4] = {a.x,a.y,a.z,a.w};
            float br[4] = {b.x,b.y,b.z,b.w};
            #pragma unroll
            for (int i = 0; i < 4; i++)
                #pragma unroll
                for (int j = 0; j < 4; j++)
                    acc[i][j] = fmaf(ar[i], br[j], acc[i][j]);
        }
        __syncthreads();
    }
    #pragma unroll
    for (int j = 0; j < 4; j++) {
        float bias = pb[db + tx*4 + j];
        #pragma unroll
        for (int i = 0; i < 4; i++)
            g_codebook[(size_t)(kb + ty*4 + i)*Dd + db + tx*4 + j] = acc[i][j] + bias;
    }
}

// ---------------- cb_sq ----------------
__global__ void cbsq_kernel() {
    int row  = blockIdx.x * 8 + (threadIdx.x >> 5);
    int lane = threadIdx.x & 31;
    const float* c = g_codebook + (size_t)row * Dd;
    float s = 0.f;
    for (int d = lane*4; d < Dd; d += 128) {
        float4 v = *(const float4*)(c + d);
        s += v.x*v.x + v.y*v.y + v.z*v.z + v.w*v.w;
    }
    #pragma unroll
    for (int off = 16; off; off >>= 1) s += __shfl_down_sync(0xffffffffu, s, off);
    if (lane == 0) g_cbsq[row] = s;
}

// ---------------- fp16 hi/lo splits ----------------
__device__ __forceinline__ void split1(float v, __half& h, __half& l) {
    h = __float2half_rn(v);
    l = __float2half_rn(v - __half2float(h));
}
__global__ void split_x_kernel(const float* __restrict__ X0, const float* __restrict__ X1) {
    size_t idx = (size_t)blockIdx.x * 256 + threadIdx.x;   // float4 index
    const size_t half_n = (size_t)Nq * Dd / 4;
    float4 v = (idx < half_n) ? ((const float4*)X0)[idx] : ((const float4*)X1)[idx - half_n];
    __half h0,h1,h2,h3,l0,l1,l2,l3;
    split1(v.x,h0,l0); split1(v.y,h1,l1); split1(v.z,h2,l2); split1(v.w,h3,l3);
    __half* ph = g_xhi + idx*4; ph[0]=h0; ph[1]=h1; ph[2]=h2; ph[3]=h3;
    __half* pl = g_xlo + idx*4; pl[0]=l0; pl[1]=l1; pl[2]=l2; pl[3]=l3;
}
__global__ void split_c_kernel() {
    size_t idx = (size_t)blockIdx.x * 256 + threadIdx.x;
    float4 v = ((const float4*)g_codebook)[idx];
    __half h0,h1,h2,h3,l0,l1,l2,l3;
    split1(v.x,h0,l0); split1(v.y,h1,l1); split1(v.z,h2,l2); split1(v.w,h3,l3);
    __half* ph = g_chi + idx*4; ph[0]=h0; ph[1]=h1; ph[2]=h2; ph[3]=h3;
    __half* pl = g_clo + idx*4; pl[0]=l0; pl[1]=l1; pl[2]=l2; pl[3]=l3;
}

// ---------------- mma.sync argmin (fp16 3-pass split) ----------------
__global__ void __launch_bounds__(256, 1) argmin_mma() {
    extern __shared__ char dsm[];
    __shared__ float sCb[NTB];
    __shared__ float sD[MT][4];
    __shared__ int   sI[MT][4];
    uint32_t sb = (smem_u32(dsm) + 1023) & ~1023u;

    const int tid = threadIdx.x, lane = tid & 31, wid = tid >> 5;
    const int wr = wid >> 2, wc = wid & 3;          // 2x4 warp grid
    const int m0 = blockIdx.x * MT;
    const int r16 = lane & 15;
    const int c8  = (lane >> 4) * 8;

    float bd[8]; int bi[8];
    #pragma unroll
    for (int s = 0; s < 8; s++) { bd[s] = INFINITY; bi[s] = 0; }

    float acc[4][4][4];

    // issue loads for pipeline step cc into stage cc&1
    auto issue = [&](int cc) {
        const int nc = cc >> 3, kc = cc & 7;
        const uint32_t st = sb + (cc & 1) * STAGE_BYTES;
        #pragma unroll
        for (int it = 0; it < 16; it++) {
            int idx = it * 256 + tid;
            int tile = idx >> 10;          // 0..3
            int rs = idx & 1023;
            int row = rs >> 3, seg = rs & 7;
            uint32_t dst = st + tile * 16384 + SWZ((uint32_t)(row * 128 + seg * 16));
            const __half* src;
            if (tile == 0)      src = g_xhi + (size_t)(m0 + row) * Dd + kc * KCH + seg * 8;
            else if (tile == 1) src = g_xlo + (size_t)(m0 + row) * Dd + kc * KCH + seg * 8;
            else if (tile == 2) src = g_chi + (size_t)(nc * NTB + row) * Dd + kc * KCH + seg * 8;
            else                src = g_clo + (size_t)(nc * NTB + row) * Dd + kc * KCH + seg * 8;
            CP_ASYNC16(dst, __cvta_generic_to_global(src));
        }
    };

    issue(0);
    CP_COMMIT();

    for (int cc = 0; cc < NCHUNKS; cc++) {
        const int nc = cc >> 3, kc = cc & 7;

        // stage cc&1 data complete (group issued in iter cc-1 or prologue)
        CP_WAIT0();
        // everyone done computing on the stage we are about to overwrite,
        // and everyone's async copies for THIS stage have landed
        __syncthreads();
        // prefetch next chunk into the other stage (overlaps compute below)
        if (cc + 1 < NCHUNKS) { issue(cc + 1); CP_COMMIT(); }

        if (kc == 0) {
            if (tid < NTB) sCb[tid] = g_cbsq[nc * NTB + tid];
            #pragma unroll
            for (int f = 0; f < 4; f++)
                #pragma unroll
                for (int n = 0; n < 4; n++)
                    #pragma unroll
                    for (int v = 0; v < 4; v++) acc[f][n][v] = 0.f;
        }

        const uint32_t tb = sb + (cc & 1) * STAGE_BYTES;
        #pragma unroll
        for (int kb = 0; kb < 4; kb++) {
            const uint32_t colb = (uint32_t)(kb * 16 + c8) * 2;
            uint32_t ah[4][4], al[4][4], bh[4][2], bl[4][2];
            #pragma unroll
            for (int f = 0; f < 4; f++) {
                uint32_t off = SWZ((uint32_t)((wr * 64 + f * 16 + r16) * 128) + colb);
                LDSM_X4(ah[f][0], ah[f][1], ah[f][2], ah[f][3], tb + T_XH + off);
                LDSM_X4(al[f][0], al[f][1], al[f][2], al[f][3], tb + T_XL + off);
            }
            #pragma unroll
            for (int np = 0; np < 2; np++) {
                uint32_t off = SWZ((uint32_t)((wc * 32 + np * 16 + r16) * 128) + colb);
                uint32_t q0, q1, q2, q3;
                LDSM_X4(q0, q1, q2, q3, tb + T_CH + off);
                bh[np*2][0] = q0; bh[np*2][1] = q2; bh[np*2+1][0] = q1; bh[np*2+1][1] = q3;
                LDSM_X4(q0, q1, q2, q3, tb + T_CL + off);
                bl[np*2][0] = q0; bl[np*2][1] = q2; bl[np*2+1][0] = q1; bl[np*2+1][1] = q3;
            }
            #pragma unroll
            for (int f = 0; f < 4; f++)
                #pragma unroll
                for (int n = 0; n < 4; n++) {
                    MMA16816(acc[f][n], ah[f], bh[n]);
                    MMA16816(acc[f][n], ah[f], bl[n]);
                    MMA16816(acc[f][n], al[f], bh[n]);
                }
        }

        if (kc == KIT - 1) {
            // epilogue for this N-chunk: dist = cbsq - 2*dot, running argmin
            #pragma unroll
            for (int f = 0; f < 4; f++)
                #pragma unroll
                for (int n = 0; n < 4; n++) {
                    int lc = wc * 32 + n * 8 + (lane & 3) * 2;
                    int gc = nc * NTB + lc;
                    float cq0 = sCb[lc], cq1 = sCb[lc + 1];
                    float d0 = fmaf(-2.f, acc[f][n][0], cq0);
                    float d1 = fmaf(-2.f, acc[f][n][1], cq1);
                    float d2 = fmaf(-2.f, acc[f][n][2], cq0);
                    float d3 = fmaf(-2.f, acc[f][n][3], cq1);
                    if (d0 < bd[f])   { bd[f] = d0;   bi[f] = gc; }
                    if (d1 < bd[f])   { bd[f] = d1;   bi[f] = gc + 1; }
                    if (d2 < bd[f+4]) { bd[f+4] = d2; bi[f+4] = gc; }
                    if (d3 < bd[f+4]) { bd[f+4] = d3; bi[f+4] = gc + 1; }
                }
        }
    }

    // cross-lane (quad) reduction with lower-index tie-break
    #pragma unroll
    for (int s = 0; s < 8; s++) {
        #pragma unroll
        for (int x = 1; x <= 2; x <<= 1) {
            float od = __shfl_xor_sync(0xffffffffu, bd[s], x);
            int   oi = __shfl_xor_sync(0xffffffffu, bi[s], x);
            if (od < bd[s] || (od == bd[s] && oi < bi[s])) { bd[s] = od; bi[s] = oi; }
        }
        int row = wr * 64 + (s & 3) * 16 + (lane >> 2) + ((s >= 4) ? 8 : 0);
        if ((lane & 3) == 0) { sD[row][wc] = bd[s]; sI[row][wc] = bi[s]; }
    }
    __syncthreads();
    if (tid < MT) {
        float best = sD[tid][0]; int bidx = sI[tid][0];
        #pragma unroll
        for (int t = 1; t < 4; t++) {
            float dv = sD[tid][t]; int iv = sI[tid][t];
            if (dv < best || (dv == best && iv < bidx)) { best = dv; bidx = iv; }
        }
        g_bi[m0 + tid] = bidx;
    }
}

// ---------------- gather + per-row MSE partials ----------------
__global__ void gather_kernel(const float* __restrict__ X0,
                              const float* __restrict__ X1,
                              float* __restrict__ out)
{
    const int m = blockIdx.x;
    const int tid = threadIdx.x;   // 128
    __shared__ float wsum[4][2];

    const int idx = g_bi[m];
    if (tid == 0) {
        int src = (m < Nq) ? 0 : 1;
        atomicAdd(&g_counts[src*Kc + idx], 1);
    }
    const float* q = g_codebook + (size_t)idx * Dd;
    const float *x, *o; float* op;
    if (m < Nq) { x = X0 + (size_t)m*Dd; o = X1 + (size_t)m*Dd; op = out + (size_t)m*Dd; }
    else { int mr = m - Nq;
           x = X1 + (size_t)mr*Dd; o = X0 + (size_t)mr*Dd; op = out + (size_t)(Nq+mr)*Dd; }

    float4 qv = *(const float4*)(q + tid*4);
    float4 xv = *(const float4*)(x + tid*4);
    float4 ov = *(const float4*)(o + tid*4);
    float dx0 = qv.x - xv.x, dx1 = qv.y - xv.y, dx2 = qv.z - xv.z, dx3 = qv.w - xv.w;
    float4 w = {xv.x + dx0, xv.y + dx1, xv.z + dx2, xv.w + dx3};
    *(float4*)(op + tid*4) = w;

    float sA = dx0*dx0 + dx1*dx1 + dx2*dx2 + dx3*dx3;
    float e0 = qv.x - ov.x, e1 = qv.y - ov.y, e2 = qv.z - ov.z, e3 = qv.w - ov.w;
    float sB = e0*e0 + e1*e1 + e2*e2 + e3*e3;
    #pragma unroll
    for (int off = 16; off; off >>= 1) {
        sA += __shfl_down_sync(0xffffffffu, sA, off);
        sB += __shfl_down_sync(0xffffffffu, sB, off);
    }
    int warp = tid >> 5, lane = tid & 31;
    if (lane == 0) { wsum[warp][0] = sA; wsum[warp][1] = sB; }
    __syncthreads();
    if (tid == 0) {
        g_rowsums[2*m]   = wsum[0][0] + wsum[1][0] + wsum[2][0] + wsum[3][0];
        g_rowsums[2*m+1] = wsum[0][1] + wsum[1][1] + wsum[2][1] + wsum[3][1];
    }
}

// ---------------- losses ----------------
__global__ void loss_kernel(float* __restrict__ out) {
    const int t = threadIdx.x;
    __shared__ double red[4][256];
    double es = 0, csr = 0, er = 0, crs = 0;
    for (int m = t; m < Nq; m += 256)      { es  += (double)g_rowsums[2*m]; csr += (double)g_rowsums[2*m+1]; }
    for (int m = Nq + t; m < Mq; m += 256) { er  += (double)g_rowsums[2*m]; crs += (double)g_rowsums[2*m+1]; }
    red[0][t]=es; red[1][t]=csr; red[2][t]=er; red[3][t]=crs;
    __syncthreads();
    for (int off = 128; off; off >>= 1) {
        if (t < off) {
            red[0][t]+=red[0][t+off]; red[1][t]+=red[1][t+off];
            red[2][t]+=red[2][t+off]; red[3][t]+=red[3][t+off];
        }
        __syncthreads();
    }
    if (t == 0) {
        const double nd = (double)Nq * (double)Dd;
        double Es = red[0][0]/nd, Csr = red[1][0]/nd, Er = red[2][0]/nd, Crs = red[3][0]/nd;
        out[(size_t)2*Nq*Dd + 0] = (float)(0.5 * Es);
        double fwd = Er + Es + 0.5*Crs + 0.5*Csr;
        out[(size_t)2*Nq*Dd + 1] = (float)(0.5*Er + 0.25*fwd);
    }
}

// ---------------- perplexity ----------------
__global__ void perp_kernel(float* __restrict__ out) {
    const int src = blockIdx.x;
    const int t = threadIdx.x;
    __shared__ float red[256];
    float h = 0.f;
    for (int k = t; k < Kc; k += 256) {
        float p = (float)g_counts[src*Kc + k] * (1.0f/(float)Nq);
        h += p * logf(p + 1e-10f);
    }
    red[t] = h;
    __syncthreads();
    for (int off = 128; off; off >>= 1) {
        if (t < off) red[t] += red[t+off];
        __syncthreads();
    }
    if (t == 0) out[(size_t)2*Nq*Dd + 2 + src] = expf(-red[0]);
}

// ---------------- launcher ----------------
extern "C" void kernel_launch(void* const* d_in, const int* in_sizes, int n_in,
                              void* d_out, int out_size)
{
    const float* scRNA = (const float*)d_in[0];
    const float* ribo  = (const float*)d_in[1];
    const float* emb   = (const float*)d_in[2];
    const float* pw    = (const float*)d_in[3];
    const float* pb    = (const float*)d_in[4];
    float* out = (float*)d_out;

    cudaFuncSetAttribute(argmin_mma, cudaFuncAttributeMaxDynamicSharedMemorySize, DSM_BYTES);

    reset_kernel<<<(2*Kc + 255)/256, 256>>>();
    codebook_gemm<<<dim3(Kc/64, Dd/64), 256>>>(emb, pw, pb);
    cbsq_kernel<<<Kc/8, 256>>>();
    split_c_kernel<<<(Kc*Dd/4)/256, 256>>>();
    split_x_kernel<<<(int)(((size_t)Mq*Dd/4)/256), 256>>>(scRNA, ribo);
    argmin_mma<<<Mq/MT, 256, DSM_BYTES>>>();
    gather_kernel<<<Mq, 128>>>(scRNA, ribo, out);
    loss_kernel<<<1, 256>>>(out);
    perp_kernel<<<2, 256>>>(out);
}

// round 7
// speedup vs baseline: 3.0251x; 1.0800x over previous
#include <cuda_runtime.h>
#include <cuda_fp16.h>
#include <math.h>
#include <stdint.h>

#define Nq 8192
#define Kc 8192
#define Dd 512
#define Mq (2*Nq)

// ---- mma-argmin tiling ----
#define MT 128                 // queries per CTA
#define NTB 128                // codes per N-chunk
#define NCB (Kc/NTB)           // 64
#define KCH 64                 // halfs per K chunk
#define KIT (Dd/KCH)           // 8
#define NCHUNKS (NCB*KIT)      // 512 pipeline steps
#define TILE_BYTES 16384       // one [128][64] half tile, swizzled
#define STAGE_BYTES 65536
#define T_XH 0
#define T_XL 16384
#define T_CH 32768
#define T_CL 49152
#define DSM_BYTES (2*STAGE_BYTES + 1024)

// ---------------- device scratch ----------------
__device__ float  g_codebook[Kc*Dd];
// tiled+swizzled staging: [rowblk][kc][128][64] halfs, 16KB per tile
__device__ __align__(16) __half t_chi[(size_t)Kc*Dd];
__device__ __align__(16) __half t_clo[(size_t)Kc*Dd];
__device__ __align__(16) __half t_xhi[(size_t)Mq*Dd];
__device__ __align__(16) __half t_xlo[(size_t)Mq*Dd];
__device__ float  g_cbsq[Kc];
__device__ int    g_bi[Mq];
__device__ int    g_counts[2*Kc];
__device__ float  g_rowsums[Mq*2];

// ---------------- helpers ----------------
__device__ __forceinline__ uint32_t smem_u32(const void* p) {
    uint32_t a;
    asm("{ .reg .u64 t; cvta.to.shared.u64 t, %1; cvt.u32.u64 %0, t; }" : "=r"(a) : "l"(p));
    return a;
}
#define SWZ(o) ((o) ^ (((o) >> 3) & 0x70))
#define MBAR_INIT(a, c) asm volatile("mbarrier.init.shared.b64 [%0], %1;" :: "r"(a), "r"(c) : "memory")
#define MBAR_EXPECT(a, b) asm volatile("mbarrier.arrive.expect_tx.shared.b64 _, [%0], %1;" :: "r"(a), "r"(b) : "memory")
#define MBAR_WAIT(a, ph) do { \
    uint32_t _m = (a), _p = (ph), _d; \
    asm volatile("{ .reg .pred p; mbarrier.try_wait.parity.acquire.cta.shared::cta.b64 p, [%1], %2; selp.b32 %0,1,0,p; }" \
        : "=r"(_d) : "r"(_m), "r"(_p) : "memory"); \
    if (!_d) { asm volatile("{ .reg .pred P1; WL_%=: mbarrier.try_wait.parity.acquire.cta.shared::cta.b64 P1, [%0], %1, 0x989680; @P1 bra.uni WD_%=; bra.uni WL_%=; WD_%=: }" \
        :: "r"(_m), "r"(_p) : "memory"); } \
} while(0)
#define BULK_G2S(dst, src, bytes, mbar) \
    asm volatile("cp.async.bulk.shared::cluster.global.mbarrier::complete_tx::bytes [%0], [%1], %2, [%3];" \
        :: "r"(dst), "l"(src), "r"(bytes), "r"(mbar) : "memory")
#define LDSM_X4(r0,r1,r2,r3,a) \
    asm volatile("ldmatrix.sync.aligned.m8n8.x4.shared.b16 {%0,%1,%2,%3}, [%4];" \
        : "=r"(r0),"=r"(r1),"=r"(r2),"=r"(r3) : "r"(a))
#define MMA16816(d,a,b) \
    asm volatile("mma.sync.aligned.m16n8k16.row.col.f32.f16.f16.f32 " \
        "{%0,%1,%2,%3}, {%4,%5,%6,%7}, {%8,%9}, {%0,%1,%2,%3};" \
        : "+f"((d)[0]),"+f"((d)[1]),"+f"((d)[2]),"+f"((d)[3]) \
        : "r"((a)[0]),"r"((a)[1]),"r"((a)[2]),"r"((a)[3]), "r"((b)[0]),"r"((b)[1]))

// ---------------- reset ----------------
__global__ void reset_kernel() {
    int i = blockIdx.x * 256 + threadIdx.x;
    if (i < 2*Kc) g_counts[i] = 0;
}

// ---------------- codebook GEMM (scalar, small) ----------------
__global__ __launch_bounds__(256) void codebook_gemm(
    const float* __restrict__ emb, const float* __restrict__ pw,
    const float* __restrict__ pb)
{
    __shared__ float Es[16][64];
    __shared__ float Ps[16][64];
    const int tid = threadIdx.x;
    const int tx = tid & 15, ty = tid >> 4;
    const int kb = blockIdx.x * 64, db = blockIdx.y * 64;
    const int lr = tid & 63, jq = tid >> 6;
    float acc[4][4];
    #pragma unroll
    for (int i = 0; i < 4; i++)
        #pragma unroll
        for (int j = 0; j < 4; j++) acc[i][j] = 0.f;
    for (int j0 = 0; j0 < Dd; j0 += 16) {
        float4 ve = *(const float4*)(emb + (size_t)(kb+lr)*Dd + j0 + jq*4);
        Es[jq*4+0][lr]=ve.x; Es[jq*4+1][lr]=ve.y; Es[jq*4+2][lr]=ve.z; Es[jq*4+3][lr]=ve.w;
        float4 vp = *(const float4*)(pw  + (size_t)(db+lr)*Dd + j0 + jq*4);
        Ps[jq*4+0][lr]=vp.x; Ps[jq*4+1][lr]=vp.y; Ps[jq*4+2][lr]=vp.z; Ps[jq*4+3][lr]=vp.w;
        __syncthreads();
        #pragma unroll
        for (int jj = 0; jj < 16; jj++) {
            float4 a = *(const float4*)&Es[jj][ty*4];
            float4 b = *(const float4*)&Ps[jj][tx*4];
            float ar[4] = {a.x,a.y,a.z,a.w};
            float br[4] = {b.x,b.y,b.z,b.w};
            #pragma unroll
            for (int i = 0; i < 4; i++)
                #pragma unroll
                for (int j = 0; j < 4; j++)
                    acc[i][j] = fmaf(ar[i], br[j], acc[i][j]);
        }
        __syncthreads();
    }
    #pragma unroll
    for (int j = 0; j < 4; j++) {
        float bias = pb[db + tx*4 + j];
        #pragma unroll
        for (int i = 0; i < 4; i++)
            g_codebook[(size_t)(kb + ty*4 + i)*Dd + db + tx*4 + j] = acc[i][j] + bias;
    }
}

// ---------------- cb_sq ----------------
__global__ void cbsq_kernel() {
    int row  = blockIdx.x * 8 + (threadIdx.x >> 5);
    int lane = threadIdx.x & 31;
    const float* c = g_codebook + (size_t)row * Dd;
    float s = 0.f;
    for (int d = lane*4; d < Dd; d += 128) {
        float4 v = *(const float4*)(c + d);
        s += v.x*v.x + v.y*v.y + v.z*v.z + v.w*v.w;
    }
    #pragma unroll
    for (int off = 16; off; off >>= 1) s += __shfl_down_sync(0xffffffffu, s, off);
    if (lane == 0) g_cbsq[row] = s;
}

// ---------------- fp16 hi/lo split into pre-swizzled tiles ----------------
// one thread = one 8-float segment -> 16B hi + 16B lo, written at the exact
// SMEM-tile-image offset so argmin can bulk-copy whole 16KB tiles.
__device__ __forceinline__ uint4 pack_hi(const float* v) {
    __half2 a = __floats2half2_rn(v[0], v[1]);
    __half2 b = __floats2half2_rn(v[2], v[3]);
    __half2 c = __floats2half2_rn(v[4], v[5]);
    __half2 d = __floats2half2_rn(v[6], v[7]);
    uint4 r; r.x = *(uint32_t*)&a; r.y = *(uint32_t*)&b; r.z = *(uint32_t*)&c; r.w = *(uint32_t*)&d;
    return r;
}
__device__ __forceinline__ uint4 pack_lo(const float* v) {
    float l[8];
    #pragma unroll
    for (int i = 0; i < 8; i++) {
        __half h = __float2half_rn(v[i]);
        l[i] = v[i] - __half2float(h);
    }
    return pack_hi(l);
}
__global__ void split_x_kernel(const float* __restrict__ X0, const float* __restrict__ X1) {
    size_t t = (size_t)blockIdx.x * 256 + threadIdx.x;   // segment id
    int m = (int)(t >> 6);
    int seg = (int)(t & 63);
    int kc = seg >> 3, s8 = seg & 7;
    const float* src = (m < Nq) ? (X0 + (size_t)m * Dd) : (X1 + (size_t)(m - Nq) * Dd);
    float v[8];
    float4 a = *(const float4*)(src + seg*8);
    float4 b = *(const float4*)(src + seg*8 + 4);
    v[0]=a.x; v[1]=a.y; v[2]=a.z; v[3]=a.w; v[4]=b.x; v[5]=b.y; v[6]=b.z; v[7]=b.w;
    size_t tile = (size_t)(m >> 7) * KIT + kc;
    uint32_t off = SWZ((uint32_t)((m & 127) * 128 + s8 * 16));
    *(uint4*)((char*)t_xhi + tile * TILE_BYTES + off) = pack_hi(v);
    *(uint4*)((char*)t_xlo + tile * TILE_BYTES + off) = pack_lo(v);
}
__global__ void split_c_kernel() {
    size_t t = (size_t)blockIdx.x * 256 + threadIdx.x;
    int m = (int)(t >> 6);
    int seg = (int)(t & 63);
    int kc = seg >> 3, s8 = seg & 7;
    const float* src = g_codebook + (size_t)m * Dd;
    float v[8];
    float4 a = *(const float4*)(src + seg*8);
    float4 b = *(const float4*)(src + seg*8 + 4);
    v[0]=a.x; v[1]=a.y; v[2]=a.z; v[3]=a.w; v[4]=b.x; v[5]=b.y; v[6]=b.z; v[7]=b.w;
    size_t tile = (size_t)(m >> 7) * KIT + kc;
    uint32_t off = SWZ((uint32_t)((m & 127) * 128 + s8 * 16));
    *(uint4*)((char*)t_chi + tile * TILE_BYTES + off) = pack_hi(v);
    *(uint4*)((char*)t_clo + tile * TILE_BYTES + off) = pack_lo(v);
}

// ---------------- mma.sync argmin (fp16 3-pass split, bulk-copy fed) ------
__global__ void __launch_bounds__(256, 1) argmin_mma() {
    extern __shared__ char dsm[];
    __shared__ float sCb[NTB];
    __shared__ float sD[MT][4];
    __shared__ int   sI[MT][4];
    __shared__ __align__(8) unsigned long long mbar[2];
    uint32_t sb = (smem_u32(dsm) + 1023) & ~1023u;
    uint32_t mb = smem_u32(mbar);

    const int tid = threadIdx.x, lane = tid & 31, wid = tid >> 5;
    const int wr = wid >> 2, wc = wid & 3;          // 2x4 warp grid
    const int m0 = blockIdx.x * MT;
    const int r16 = lane & 15;
    const int c8  = (lane >> 4) * 8;

    float bd[8]; int bi[8];
    #pragma unroll
    for (int s = 0; s < 8; s++) { bd[s] = INFINITY; bi[s] = 0; }

    float acc[4][4][4];

    const size_t xblk = (size_t)(m0 >> 7) * KIT;

    // issue one chunk's 4 tiles via bulk copy (single thread)
    auto issue = [&](int cc) {
        const int nc = cc >> 3, kc = cc & 7;
        const uint32_t st = sb + (cc & 1) * STAGE_BYTES;
        const uint32_t mba = mb + (cc & 1) * 8;
        MBAR_EXPECT(mba, STAGE_BYTES);
        const char* xh = (const char*)t_xhi + (xblk + kc) * TILE_BYTES;
        const char* xl = (const char*)t_xlo + (xblk + kc) * TILE_BYTES;
        const char* ch = (const char*)t_chi + ((size_t)nc * KIT + kc) * TILE_BYTES;
        const char* cl = (const char*)t_clo + ((size_t)nc * KIT + kc) * TILE_BYTES;
        BULK_G2S(st + T_XH, __cvta_generic_to_global(xh), TILE_BYTES, mba);
        BULK_G2S(st + T_XL, __cvta_generic_to_global(xl), TILE_BYTES, mba);
        BULK_G2S(st + T_CH, __cvta_generic_to_global(ch), TILE_BYTES, mba);
        BULK_G2S(st + T_CL, __cvta_generic_to_global(cl), TILE_BYTES, mba);
    };

    if (tid == 0) { MBAR_INIT(mb, 1); MBAR_INIT(mb + 8, 1); }
    __syncthreads();
    if (tid == 0) issue(0);

    int ph[2] = {0, 0};

    for (int cc = 0; cc < NCHUNKS; cc++) {
        const int nc = cc >> 3, kc = cc & 7;
        const int s = cc & 1;

        MBAR_WAIT(mb + s*8, ph[s]); ph[s] ^= 1;
        __syncthreads();                 // all threads done with stage s^1 (chunk cc-1)
        if (tid == 0 && cc + 1 < NCHUNKS) issue(cc + 1);

        if (kc == 0) {
            if (tid < NTB) sCb[tid] = g_cbsq[nc * NTB + tid];
            #pragma unroll
            for (int f = 0; f < 4; f++)
                #pragma unroll
                for (int n = 0; n < 4; n++)
                    #pragma unroll
                    for (int v = 0; v < 4; v++) acc[f][n][v] = 0.f;
        }

        const uint32_t tb = sb + s * STAGE_BYTES;
        #pragma unroll
        for (int kb = 0; kb < 4; kb++) {
            const uint32_t colb = (uint32_t)(kb * 16 + c8) * 2;
            uint32_t ah[4][4], al[4][4], bh[4][2], bl[4][2];
            #pragma unroll
            for (int f = 0; f < 4; f++) {
                uint32_t off = SWZ((uint32_t)((wr * 64 + f * 16 + r16) * 128) + colb);
                LDSM_X4(ah[f][0], ah[f][1], ah[f][2], ah[f][3], tb + T_XH + off);
                LDSM_X4(al[f][0], al[f][1], al[f][2], al[f][3], tb + T_XL + off);
            }
            #pragma unroll
            for (int np = 0; np < 2; np++) {
                uint32_t off = SWZ((uint32_t)((wc * 32 + np * 16 + r16) * 128) + colb);
                uint32_t q0, q1, q2, q3;
                LDSM_X4(q0, q1, q2, q3, tb + T_CH + off);
                bh[np*2][0] = q0; bh[np*2][1] = q2; bh[np*2+1][0] = q1; bh[np*2+1][1] = q3;
                LDSM_X4(q0, q1, q2, q3, tb + T_CL + off);
                bl[np*2][0] = q0; bl[np*2][1] = q2; bl[np*2+1][0] = q1; bl[np*2+1][1] = q3;
            }
            #pragma unroll
            for (int f = 0; f < 4; f++)
                #pragma unroll
                for (int n = 0; n < 4; n++) {
                    MMA16816(acc[f][n], ah[f], bh[n]);
                    MMA16816(acc[f][n], ah[f], bl[n]);
                    MMA16816(acc[f][n], al[f], bh[n]);
                }
        }

        if (kc == KIT - 1) {
            // epilogue: dist = cbsq - 2*dot, running argmin
            #pragma unroll
            for (int f = 0; f < 4; f++)
                #pragma unroll
                for (int n = 0; n < 4; n++) {
                    int lc = wc * 32 + n * 8 + (lane & 3) * 2;
                    int gc = nc * NTB + lc;
                    float cq0 = sCb[lc], cq1 = sCb[lc + 1];
                    float d0 = fmaf(-2.f, acc[f][n][0], cq0);
                    float d1 = fmaf(-2.f, acc[f][n][1], cq1);
                    float d2 = fmaf(-2.f, acc[f][n][2], cq0);
                    float d3 = fmaf(-2.f, acc[f][n][3], cq1);
                    if (d0 < bd[f])   { bd[f] = d0;   bi[f] = gc; }
                    if (d1 < bd[f])   { bd[f] = d1;   bi[f] = gc + 1; }
                    if (d2 < bd[f+4]) { bd[f+4] = d2; bi[f+4] = gc; }
                    if (d3 < bd[f+4]) { bd[f+4] = d3; bi[f+4] = gc + 1; }
                }
        }
    }

    // cross-lane (quad) reduction with lower-index tie-break
    #pragma unroll
    for (int s = 0; s < 8; s++) {
        #pragma unroll
        for (int x = 1; x <= 2; x <<= 1) {
            float od = __shfl_xor_sync(0xffffffffu, bd[s], x);
            int   oi = __shfl_xor_sync(0xffffffffu, bi[s], x);
            if (od < bd[s] || (od == bd[s] && oi < bi[s])) { bd[s] = od; bi[s] = oi; }
        }
        int row = wr * 64 + (s & 3) * 16 + (lane >> 2) + ((s >= 4) ? 8 : 0);
        if ((lane & 3) == 0) { sD[row][wc] = bd[s]; sI[row][wc] = bi[s]; }
    }
    __syncthreads();
    if (tid < MT) {
        float best = sD[tid][0]; int bidx = sI[tid][0];
        #pragma unroll
        for (int t = 1; t < 4; t++) {
            float dv = sD[tid][t]; int iv = sI[tid][t];
            if (dv < best || (dv == best && iv < bidx)) { best = dv; bidx = iv; }
        }
        g_bi[m0 + tid] = bidx;
    }
}

// ---------------- gather + per-row MSE partials ----------------
__global__ void gather_kernel(const float* __restrict__ X0,
                              const float* __restrict__ X1,
                              float* __restrict__ out)
{
    const int m = blockIdx.x;
    const int tid = threadIdx.x;   // 128
    __shared__ float wsum[4][2];

    const int idx = g_bi[m];
    if (tid == 0) {
        int src = (m < Nq) ? 0 : 1;
        atomicAdd(&g_counts[src*Kc + idx], 1);
    }
    const float* q = g_codebook + (size_t)idx * Dd;
    const float *x, *o; float* op;
    if (m < Nq) { x = X0 + (size_t)m*Dd; o = X1 + (size_t)m*Dd; op = out + (size_t)m*Dd; }
    else { int mr = m - Nq;
           x = X1 + (size_t)mr*Dd; o = X0 + (size_t)mr*Dd; op = out + (size_t)(Nq+mr)*Dd; }

    float4 qv = *(const float4*)(q + tid*4);
    float4 xv = *(const float4*)(x + tid*4);
    float4 ov = *(const float4*)(o + tid*4);
    float dx0 = qv.x - xv.x, dx1 = qv.y - xv.y, dx2 = qv.z - xv.z, dx3 = qv.w - xv.w;
    float4 w = {xv.x + dx0, xv.y + dx1, xv.z + dx2, xv.w + dx3};
    *(float4*)(op + tid*4) = w;

    float sA = dx0*dx0 + dx1*dx1 + dx2*dx2 + dx3*dx3;
    float e0 = qv.x - ov.x, e1 = qv.y - ov.y, e2 = qv.z - ov.z, e3 = qv.w - ov.w;
    float sB = e0*e0 + e1*e1 + e2*e2 + e3*e3;
    #pragma unroll
    for (int off = 16; off; off >>= 1) {
        sA += __shfl_down_sync(0xffffffffu, sA, off);
        sB += __shfl_down_sync(0xffffffffu, sB, off);
    }
    int warp = tid >> 5, lane = tid & 31;
    if (lane == 0) { wsum[warp][0] = sA; wsum[warp][1] = sB; }
    __syncthreads();
    if (tid == 0) {
        g_rowsums[2*m]   = wsum[0][0] + wsum[1][0] + wsum[2][0] + wsum[3][0];
        g_rowsums[2*m+1] = wsum[0][1] + wsum[1][1] + wsum[2][1] + wsum[3][1];
    }
}

// ---------------- losses ----------------
__global__ void loss_kernel(float* __restrict__ out) {
    const int t = threadIdx.x;
    __shared__ double red[4][256];
    double es = 0, csr = 0, er = 0, crs = 0;
    for (int m = t; m < Nq; m += 256)      { es  += (double)g_rowsums[2*m]; csr += (double)g_rowsums[2*m+1]; }
    for (int m = Nq + t; m < Mq; m += 256) { er  += (double)g_rowsums[2*m]; crs += (double)g_rowsums[2*m+1]; }
    red[0][t]=es; red[1][t]=csr; red[2][t]=er; red[3][t]=crs;
    __syncthreads();
    for (int off = 128; off; off >>= 1) {
        if (t < off) {
            red[0][t]+=red[0][t+off]; red[1][t]+=red[1][t+off];
            red[2][t]+=red[2][t+off]; red[3][t]+=red[3][t+off];
        }
        __syncthreads();
    }
    if (t == 0) {
        const double nd = (double)Nq * (double)Dd;
        double Es = red[0][0]/nd, Csr = red[1][0]/nd, Er = red[2][0]/nd, Crs = red[3][0]/nd;
        out[(size_t)2*Nq*Dd + 0] = (float)(0.5 * Es);
        double fwd = Er + Es + 0.5*Crs + 0.5*Csr;
        out[(size_t)2*Nq*Dd + 1] = (float)(0.5*Er + 0.25*fwd);
    }
}

// ---------------- perplexity ----------------
__global__ void perp_kernel(float* __restrict__ out) {
    const int src = blockIdx.x;
    const int t = threadIdx.x;
    __shared__ float red[256];
    float h = 0.f;
    for (int k = t; k < Kc; k += 256) {
        float p = (float)g_counts[src*Kc + k] * (1.0f/(float)Nq);
        h += p * logf(p + 1e-10f);
    }
    red[t] = h;
    __syncthreads();
    for (int off = 128; off; off >>= 1) {
        if (t < off) red[t] += red[t+off];
        __syncthreads();
    }
    if (t == 0) out[(size_t)2*Nq*Dd + 2 + src] = expf(-red[0]);
}

// ---------------- launcher ----------------
extern "C" void kernel_launch(void* const* d_in, const int* in_sizes, int n_in,
                              void* d_out, int out_size)
{
    const float* scRNA = (const float*)d_in[0];
    const float* ribo  = (const float*)d_in[1];
    const float* emb   = (const float*)d_in[2];
    const float* pw    = (const float*)d_in[3];
    const float* pb    = (const float*)d_in[4];
    float* out = (float*)d_out;

    cudaFuncSetAttribute(argmin_mma, cudaFuncAttributeMaxDynamicSharedMemorySize, DSM_BYTES);

    reset_kernel<<<(2*Kc + 255)/256, 256>>>();
    codebook_gemm<<<dim3(Kc/64, Dd/64), 256>>>(emb, pw, pb);
    cbsq_kernel<<<Kc/8, 256>>>();
    split_c_kernel<<<(int)(((size_t)Kc*Dd/8)/256), 256>>>();
    split_x_kernel<<<(int)(((size_t)Mq*Dd/8)/256), 256>>>(scRNA, ribo);
    argmin_mma<<<Mq/MT, 256, DSM_BYTES>>>();
    gather_kernel<<<Mq, 128>>>(scRNA, ribo, out);
    loss_kernel<<<1, 256>>>(out);
    perp_kernel<<<2, 256>>>(out);
}

// round 8
// speedup vs baseline: 3.1134x; 1.0292x over previous
#include <cuda_runtime.h>
#include <cuda_fp16.h>
#include <math.h>
#include <stdint.h>

#define Nq 8192
#define Kc 8192
#define Dd 512
#define Mq (2*Nq)

// ---- mma-argmin tiling ----
#define MT 128                 // queries per CTA
#define NTB 256                // codes per N-chunk (CTA tile 128x256)
#define NCB (Kc/NTB)           // 32
#define KCH 64                 // halfs per K chunk
#define KIT (Dd/KCH)           // 8
#define NCHUNKS (NCB*KIT)      // 256 pipeline steps
#define TILE_BYTES 16384       // one [128][64] half tile, swizzled
#define T_XH 0
#define T_XL 16384
#define T_CH 32768
#define T_CL 65536
#define STAGE_BYTES 98304      // 96KB per stage
#define DSM_BYTES (2*STAGE_BYTES + 1024)

// ---------------- device scratch ----------------
__device__ float  g_codebook[Kc*Dd];
// tiled+swizzled staging: [rowblk][kc][128][64] halfs, 16KB per tile
__device__ __align__(16) __half t_chi[(size_t)Kc*Dd];
__device__ __align__(16) __half t_clo[(size_t)Kc*Dd];
__device__ __align__(16) __half t_xhi[(size_t)Mq*Dd];
__device__ __align__(16) __half t_xlo[(size_t)Mq*Dd];
__device__ float  g_cbsq[Kc];
__device__ int    g_bi[Mq];
__device__ int    g_counts[2*Kc];
__device__ float  g_rowsums[Mq*2];

// ---------------- helpers ----------------
__device__ __forceinline__ uint32_t smem_u32(const void* p) {
    uint32_t a;
    asm("{ .reg .u64 t; cvta.to.shared.u64 t, %1; cvt.u32.u64 %0, t; }" : "=r"(a) : "l"(p));
    return a;
}
#define SWZ(o) ((o) ^ (((o) >> 3) & 0x70))
#define MBAR_INIT(a, c) asm volatile("mbarrier.init.shared.b64 [%0], %1;" :: "r"(a), "r"(c) : "memory")
#define MBAR_EXPECT(a, b) asm volatile("mbarrier.arrive.expect_tx.shared.b64 _, [%0], %1;" :: "r"(a), "r"(b) : "memory")
#define MBAR_WAIT(a, ph) do { \
    uint32_t _m = (a), _p = (ph), _d; \
    asm volatile("{ .reg .pred p; mbarrier.try_wait.parity.acquire.cta.shared::cta.b64 p, [%1], %2; selp.b32 %0,1,0,p; }" \
        : "=r"(_d) : "r"(_m), "r"(_p) : "memory"); \
    if (!_d) { asm volatile("{ .reg .pred P1; WL_%=: mbarrier.try_wait.parity.acquire.cta.shared::cta.b64 P1, [%0], %1, 0x989680; @P1 bra.uni WD_%=; bra.uni WL_%=; WD_%=: }" \
        :: "r"(_m), "r"(_p) : "memory"); } \
} while(0)
#define BULK_G2S(dst, src, bytes, mbar) \
    asm volatile("cp.async.bulk.shared::cluster.global.mbarrier::complete_tx::bytes [%0], [%1], %2, [%3];" \
        :: "r"(dst), "l"(src), "r"(bytes), "r"(mbar) : "memory")
#define LDSM_X4(r0,r1,r2,r3,a) \
    asm volatile("ldmatrix.sync.aligned.m8n8.x4.shared.b16 {%0,%1,%2,%3}, [%4];" \
        : "=r"(r0),"=r"(r1),"=r"(r2),"=r"(r3) : "r"(a))
#define MMA16816(d,a,b) \
    asm volatile("mma.sync.aligned.m16n8k16.row.col.f32.f16.f16.f32 " \
        "{%0,%1,%2,%3}, {%4,%5,%6,%7}, {%8,%9}, {%0,%1,%2,%3};" \
        : "+f"((d)[0]),"+f"((d)[1]),"+f"((d)[2]),"+f"((d)[3]) \
        : "r"((a)[0]),"r"((a)[1]),"r"((a)[2]),"r"((a)[3]), "r"((b)[0]),"r"((b)[1]))

// ---------------- reset ----------------
__global__ void reset_kernel() {
    int i = blockIdx.x * 256 + threadIdx.x;
    if (i < 2*Kc) g_counts[i] = 0;
}

// ---------------- codebook GEMM (scalar, small) ----------------
__global__ __launch_bounds__(256) void codebook_gemm(
    const float* __restrict__ emb, const float* __restrict__ pw,
    const float* __restrict__ pb)
{
    __shared__ float Es[16][64];
    __shared__ float Ps[16][64];
    const int tid = threadIdx.x;
    const int tx = tid & 15, ty = tid >> 4;
    const int kb = blockIdx.x * 64, db = blockIdx.y * 64;
    const int lr = tid & 63, jq = tid >> 6;
    float acc[4][4];
    #pragma unroll
    for (int i = 0; i < 4; i++)
        #pragma unroll
        for (int j = 0; j < 4; j++) acc[i][j] = 0.f;
    for (int j0 = 0; j0 < Dd; j0 += 16) {
        float4 ve = *(const float4*)(emb + (size_t)(kb+lr)*Dd + j0 + jq*4);
        Es[jq*4+0][lr]=ve.x; Es[jq*4+1][lr]=ve.y; Es[jq*4+2][lr]=ve.z; Es[jq*4+3][lr]=ve.w;
        float4 vp = *(const float4*)(pw  + (size_t)(db+lr)*Dd + j0 + jq*4);
        Ps[jq*4+0][lr]=vp.x; Ps[jq*4+1][lr]=vp.y; Ps[jq*4+2][lr]=vp.z; Ps[jq*4+3][lr]=vp.w;
        __syncthreads();
        #pragma unroll
        for (int jj = 0; jj < 16; jj++) {
            float4 a = *(const float4*)&Es[jj][ty*4];
            float4 b = *(const float4*)&Ps[jj][tx*4];
            float ar[4] = {a.x,a.y,a.z,a.w};
            float br[4] = {b.x,b.y,b.z,b.w};
            #pragma unroll
            for (int i = 0; i < 4; i++)
                #pragma unroll
                for (int j = 0; j < 4; j++)
                    acc[i][j] = fmaf(ar[i], br[j], acc[i][j]);
        }
        __syncthreads();
    }
    #pragma unroll
    for (int j = 0; j < 4; j++) {
        float bias = pb[db + tx*4 + j];
        #pragma unroll
        for (int i = 0; i < 4; i++)
            g_codebook[(size_t)(kb + ty*4 + i)*Dd + db + tx*4 + j] = acc[i][j] + bias;
    }
}

// ---------------- cb_sq ----------------
__global__ void cbsq_kernel() {
    int row  = blockIdx.x * 8 + (threadIdx.x >> 5);
    int lane = threadIdx.x & 31;
    const float* c = g_codebook + (size_t)row * Dd;
    float s = 0.f;
    for (int d = lane*4; d < Dd; d += 128) {
        float4 v = *(const float4*)(c + d);
        s += v.x*v.x + v.y*v.y + v.z*v.z + v.w*v.w;
    }
    #pragma unroll
    for (int off = 16; off; off >>= 1) s += __shfl_down_sync(0xffffffffu, s, off);
    if (lane == 0) g_cbsq[row] = s;
}

// ---------------- fp16 hi/lo split into pre-swizzled tiles ----------------
__device__ __forceinline__ uint4 pack_hi(const float* v) {
    __half2 a = __floats2half2_rn(v[0], v[1]);
    __half2 b = __floats2half2_rn(v[2], v[3]);
    __half2 c = __floats2half2_rn(v[4], v[5]);
    __half2 d = __floats2half2_rn(v[6], v[7]);
    uint4 r; r.x = *(uint32_t*)&a; r.y = *(uint32_t*)&b; r.z = *(uint32_t*)&c; r.w = *(uint32_t*)&d;
    return r;
}
__device__ __forceinline__ uint4 pack_lo(const float* v) {
    float l[8];
    #pragma unroll
    for (int i = 0; i < 8; i++) {
        __half h = __float2half_rn(v[i]);
        l[i] = v[i] - __half2float(h);
    }
    return pack_hi(l);
}
__global__ void split_x_kernel(const float* __restrict__ X0, const float* __restrict__ X1) {
    size_t t = (size_t)blockIdx.x * 256 + threadIdx.x;   // segment id
    int m = (int)(t >> 6);
    int seg = (int)(t & 63);
    int kc = seg >> 3, s8 = seg & 7;
    const float* src = (m < Nq) ? (X0 + (size_t)m * Dd) : (X1 + (size_t)(m - Nq) * Dd);
    float v[8];
    float4 a = *(const float4*)(src + seg*8);
    float4 b = *(const float4*)(src + seg*8 + 4);
    v[0]=a.x; v[1]=a.y; v[2]=a.z; v[3]=a.w; v[4]=b.x; v[5]=b.y; v[6]=b.z; v[7]=b.w;
    size_t tile = (size_t)(m >> 7) * KIT + kc;
    uint32_t off = SWZ((uint32_t)((m & 127) * 128 + s8 * 16));
    *(uint4*)((char*)t_xhi + tile * TILE_BYTES + off) = pack_hi(v);
    *(uint4*)((char*)t_xlo + tile * TILE_BYTES + off) = pack_lo(v);
}
__global__ void split_c_kernel() {
    size_t t = (size_t)blockIdx.x * 256 + threadIdx.x;
    int m = (int)(t >> 6);
    int seg = (int)(t & 63);
    int kc = seg >> 3, s8 = seg & 7;
    const float* src = g_codebook + (size_t)m * Dd;
    float v[8];
    float4 a = *(const float4*)(src + seg*8);
    float4 b = *(const float4*)(src + seg*8 + 4);
    v[0]=a.x; v[1]=a.y; v[2]=a.z; v[3]=a.w; v[4]=b.x; v[5]=b.y; v[6]=b.z; v[7]=b.w;
    size_t tile = (size_t)(m >> 7) * KIT + kc;
    uint32_t off = SWZ((uint32_t)((m & 127) * 128 + s8 * 16));
    *(uint4*)((char*)t_chi + tile * TILE_BYTES + off) = pack_hi(v);
    *(uint4*)((char*)t_clo + tile * TILE_BYTES + off) = pack_lo(v);
}

// ---------------- mma.sync argmin (fp16 3-pass split, 128x256 CTA tile) ---
__global__ void __launch_bounds__(256, 1) argmin_mma() {
    extern __shared__ char dsm[];
    __shared__ float sCb[NTB];
    __shared__ float sD[MT][4];
    __shared__ int   sI[MT][4];
    __shared__ __align__(8) unsigned long long mbar[2];
    uint32_t sb = (smem_u32(dsm) + 1023) & ~1023u;
    uint32_t mb = smem_u32(mbar);

    const int tid = threadIdx.x, lane = tid & 31, wid = tid >> 5;
    const int wr = wid >> 2, wc = wid & 3;          // 2x4 warp grid, 64x64 per warp
    const int m0 = blockIdx.x * MT;
    const int r16 = lane & 15;
    const int c8  = (lane >> 4) * 8;

    float bd[8]; int bi[8];
    #pragma unroll
    for (int s = 0; s < 8; s++) { bd[s] = INFINITY; bi[s] = 0; }

    float acc[4][8][4];    // 128 regs: rows f*16, cols n*8 within 64x64 warp tile

    const size_t xblk = (size_t)(m0 >> 7) * KIT;

    // issue one chunk's tiles via bulk copy (single thread): X hi/lo + 2x C hi/lo
    auto issue = [&](int cc) {
        const int nc = cc >> 3, kc = cc & 7;
        const uint32_t st = sb + (cc & 1) * STAGE_BYTES;
        const uint32_t mba = mb + (cc & 1) * 8;
        MBAR_EXPECT(mba, STAGE_BYTES);
        const char* xh = (const char*)t_xhi + (xblk + kc) * TILE_BYTES;
        const char* xl = (const char*)t_xlo + (xblk + kc) * TILE_BYTES;
        const char* ch0 = (const char*)t_chi + ((size_t)(2*nc)   * KIT + kc) * TILE_BYTES;
        const char* ch1 = (const char*)t_chi + ((size_t)(2*nc+1) * KIT + kc) * TILE_BYTES;
        const char* cl0 = (const char*)t_clo + ((size_t)(2*nc)   * KIT + kc) * TILE_BYTES;
        const char* cl1 = (const char*)t_clo + ((size_t)(2*nc+1) * KIT + kc) * TILE_BYTES;
        BULK_G2S(st + T_XH,               __cvta_generic_to_global(xh),  TILE_BYTES, mba);
        BULK_G2S(st + T_XL,               __cvta_generic_to_global(xl),  TILE_BYTES, mba);
        BULK_G2S(st + T_CH,               __cvta_generic_to_global(ch0), TILE_BYTES, mba);
        BULK_G2S(st + T_CH + TILE_BYTES,  __cvta_generic_to_global(ch1), TILE_BYTES, mba);
        BULK_G2S(st + T_CL,               __cvta_generic_to_global(cl0), TILE_BYTES, mba);
        BULK_G2S(st + T_CL + TILE_BYTES,  __cvta_generic_to_global(cl1), TILE_BYTES, mba);
    };

    if (tid == 0) { MBAR_INIT(mb, 1); MBAR_INIT(mb + 8, 1); }
    __syncthreads();
    if (tid == 0) issue(0);

    int ph[2] = {0, 0};

    for (int cc = 0; cc < NCHUNKS; cc++) {
        const int nc = cc >> 3, kc = cc & 7;
        const int s = cc & 1;

        MBAR_WAIT(mb + s*8, ph[s]); ph[s] ^= 1;
        __syncthreads();                 // all threads done with the other stage
        if (tid == 0 && cc + 1 < NCHUNKS) issue(cc + 1);

        if (kc == 0) {
            sCb[tid] = g_cbsq[nc * NTB + tid];
            #pragma unroll
            for (int f = 0; f < 4; f++)
                #pragma unroll
                for (int n = 0; n < 8; n++)
                    #pragma unroll
                    for (int v = 0; v < 4; v++) acc[f][n][v] = 0.f;
        }

        const uint32_t tb = sb + s * STAGE_BYTES;
        #pragma unroll
        for (int kb = 0; kb < 4; kb++) {
            const uint32_t colb = (uint32_t)(kb * 16 + c8) * 2;
            uint32_t ah[4][4], al[4][4], bh[8][2], bl[8][2];
            #pragma unroll
            for (int f = 0; f < 4; f++) {
                uint32_t off = SWZ((uint32_t)((wr * 64 + f * 16 + r16) * 128) + colb);
                LDSM_X4(ah[f][0], ah[f][1], ah[f][2], ah[f][3], tb + T_XH + off);
                LDSM_X4(al[f][0], al[f][1], al[f][2], al[f][3], tb + T_XL + off);
            }
            #pragma unroll
            for (int np = 0; np < 4; np++) {
                int brow = wc * 64 + np * 16 + r16;
                uint32_t off = (uint32_t)((brow >> 7) * TILE_BYTES)
                             + SWZ((uint32_t)((brow & 127) * 128) + colb);
                uint32_t q0, q1, q2, q3;
                LDSM_X4(q0, q1, q2, q3, tb + T_CH + off);
                bh[np*2][0] = q0; bh[np*2][1] = q2; bh[np*2+1][0] = q1; bh[np*2+1][1] = q3;
                LDSM_X4(q0, q1, q2, q3, tb + T_CL + off);
                bl[np*2][0] = q0; bl[np*2][1] = q2; bl[np*2+1][0] = q1; bl[np*2+1][1] = q3;
            }
            #pragma unroll
            for (int f = 0; f < 4; f++)
                #pragma unroll
                for (int n = 0; n < 8; n++) {
                    MMA16816(acc[f][n], ah[f], bh[n]);
                    MMA16816(acc[f][n], ah[f], bl[n]);
                    MMA16816(acc[f][n], al[f], bh[n]);
                }
        }

        if (kc == KIT - 1) {
            // epilogue: dist = cbsq - 2*dot, running argmin
            #pragma unroll
            for (int f = 0; f < 4; f++)
                #pragma unroll
                for (int n = 0; n < 8; n++) {
                    int lc = wc * 64 + n * 8 + (lane & 3) * 2;
                    int gc = nc * NTB + lc;
                    float cq0 = sCb[lc], cq1 = sCb[lc + 1];
                    float d0 = fmaf(-2.f, acc[f][n][0], cq0);
                    float d1 = fmaf(-2.f, acc[f][n][1], cq1);
                    float d2 = fmaf(-2.f, acc[f][n][2], cq0);
                    float d3 = fmaf(-2.f, acc[f][n][3], cq1);
                    if (d0 < bd[f])   { bd[f] = d0;   bi[f] = gc; }
                    if (d1 < bd[f])   { bd[f] = d1;   bi[f] = gc + 1; }
                    if (d2 < bd[f+4]) { bd[f+4] = d2; bi[f+4] = gc; }
                    if (d3 < bd[f+4]) { bd[f+4] = d3; bi[f+4] = gc + 1; }
                }
        }
    }

    // cross-lane (quad) reduction with lower-index tie-break
    #pragma unroll
    for (int s = 0; s < 8; s++) {
        #pragma unroll
        for (int x = 1; x <= 2; x <<= 1) {
            float od = __shfl_xor_sync(0xffffffffu, bd[s], x);
            int   oi = __shfl_xor_sync(0xffffffffu, bi[s], x);
            if (od < bd[s] || (od == bd[s] && oi < bi[s])) { bd[s] = od; bi[s] = oi; }
        }
        int row = wr * 64 + (s & 3) * 16 + (lane >> 2) + ((s >= 4) ? 8 : 0);
        if ((lane & 3) == 0) { sD[row][wc] = bd[s]; sI[row][wc] = bi[s]; }
    }
    __syncthreads();
    if (tid < MT) {
        float best = sD[tid][0]; int bidx = sI[tid][0];
        #pragma unroll
        for (int t = 1; t < 4; t++) {
            float dv = sD[tid][t]; int iv = sI[tid][t];
            if (dv < best || (dv == best && iv < bidx)) { best = dv; bidx = iv; }
        }
        g_bi[m0 + tid] = bidx;
    }
}

// ---------------- gather + per-row MSE partials ----------------
__global__ void gather_kernel(const float* __restrict__ X0,
                              const float* __restrict__ X1,
                              float* __restrict__ out)
{
    const int m = blockIdx.x;
    const int tid = threadIdx.x;   // 128
    __shared__ float wsum[4][2];

    const int idx = g_bi[m];
    if (tid == 0) {
        int src = (m < Nq) ? 0 : 1;
        atomicAdd(&g_counts[src*Kc + idx], 1);
    }
    const float* q = g_codebook + (size_t)idx * Dd;
    const float *x, *o; float* op;
    if (m < Nq) { x = X0 + (size_t)m*Dd; o = X1 + (size_t)m*Dd; op = out + (size_t)m*Dd; }
    else { int mr = m - Nq;
           x = X1 + (size_t)mr*Dd; o = X0 + (size_t)mr*Dd; op = out + (size_t)(Nq+mr)*Dd; }

    float4 qv = *(const float4*)(q + tid*4);
    float4 xv = *(const float4*)(x + tid*4);
    float4 ov = *(const float4*)(o + tid*4);
    float dx0 = qv.x - xv.x, dx1 = qv.y - xv.y, dx2 = qv.z - xv.z, dx3 = qv.w - xv.w;
    float4 w = {xv.x + dx0, xv.y + dx1, xv.z + dx2, xv.w + dx3};
    *(float4*)(op + tid*4) = w;

    float sA = dx0*dx0 + dx1*dx1 + dx2*dx2 + dx3*dx3;
    float e0 = qv.x - ov.x, e1 = qv.y - ov.y, e2 = qv.z - ov.z, e3 = qv.w - ov.w;
    float sB = e0*e0 + e1*e1 + e2*e2 + e3*e3;
    #pragma unroll
    for (int off = 16; off; off >>= 1) {
        sA += __shfl_down_sync(0xffffffffu, sA, off);
        sB += __shfl_down_sync(0xffffffffu, sB, off);
    }
    int warp = tid >> 5, lane = tid & 31;
    if (lane == 0) { wsum[warp][0] = sA; wsum[warp][1] = sB; }
    __syncthreads();
    if (tid == 0) {
        g_rowsums[2*m]   = wsum[0][0] + wsum[1][0] + wsum[2][0] + wsum[3][0];
        g_rowsums[2*m+1] = wsum[0][1] + wsum[1][1] + wsum[2][1] + wsum[3][1];
    }
}

// ---------------- losses ----------------
__global__ void loss_kernel(float* __restrict__ out) {
    const int t = threadIdx.x;
    __shared__ double red[4][256];
    double es = 0, csr = 0, er = 0, crs = 0;
    for (int m = t; m < Nq; m += 256)      { es  += (double)g_rowsums[2*m]; csr += (double)g_rowsums[2*m+1]; }
    for (int m = Nq + t; m < Mq; m += 256) { er  += (double)g_rowsums[2*m]; crs += (double)g_rowsums[2*m+1]; }
    red[0][t]=es; red[1][t]=csr; red[2][t]=er; red[3][t]=crs;
    __syncthreads();
    for (int off = 128; off; off >>= 1) {
        if (t < off) {
            red[0][t]+=red[0][t+off]; red[1][t]+=red[1][t+off];
            red[2][t]+=red[2][t+off]; red[3][t]+=red[3][t+off];
        }
        __syncthreads();
    }
    if (t == 0) {
        const double nd = (double)Nq * (double)Dd;
        double Es = red[0][0]/nd, Csr = red[1][0]/nd, Er = red[2][0]/nd, Crs = red[3][0]/nd;
        out[(size_t)2*Nq*Dd + 0] = (float)(0.5 * Es);
        double fwd = Er + Es + 0.5*Crs + 0.5*Csr;
        out[(size_t)2*Nq*Dd + 1] = (float)(0.5*Er + 0.25*fwd);
    }
}

// ---------------- perplexity ----------------
__global__ void perp_kernel(float* __restrict__ out) {
    const int src = blockIdx.x;
    const int t = threadIdx.x;
    __shared__ float red[256];
    float h = 0.f;
    for (int k = t; k < Kc; k += 256) {
        float p = (float)g_counts[src*Kc + k] * (1.0f/(float)Nq);
        h += p * logf(p + 1e-10f);
    }
    red[t] = h;
    __syncthreads();
    for (int off = 128; off; off >>= 1) {
        if (t < off) red[t] += red[t+off];
        __syncthreads();
    }
    if (t == 0) out[(size_t)2*Nq*Dd + 2 + src] = expf(-red[0]);
}

// ---------------- launcher ----------------
extern "C" void kernel_launch(void* const* d_in, const int* in_sizes, int n_in,
                              void* d_out, int out_size)
{
    const float* scRNA = (const float*)d_in[0];
    const float* ribo  = (const float*)d_in[1];
    const float* emb   = (const float*)d_in[2];
    const float* pw    = (const float*)d_in[3];
    const float* pb    = (const float*)d_in[4];
    float* out = (float*)d_out;

    cudaFuncSetAttribute(argmin_mma, cudaFuncAttributeMaxDynamicSharedMemorySize, DSM_BYTES);

    reset_kernel<<<(2*Kc + 255)/256, 256>>>();
    codebook_gemm<<<dim3(Kc/64, Dd/64), 256>>>(emb, pw, pb);
    cbsq_kernel<<<Kc/8, 256>>>();
    split_c_kernel<<<(int)(((size_t)Kc*Dd/8)/256), 256>>>();
    split_x_kernel<<<(int)(((size_t)Mq*Dd/8)/256), 256>>>(scRNA, ribo);
    argmin_mma<<<Mq/MT, 256, DSM_BYTES>>>();
    gather_kernel<<<Mq, 128>>>(scRNA, ribo, out);
    loss_kernel<<<1, 256>>>(out);
    perp_kernel<<<2, 256>>>(out);
}